// round 14
// baseline (speedup 1.0000x reference)
#include <cuda_runtime.h>
#include <math.h>

// Problem constants: B=2, N=4096, D=256, H=64, K=16
#define OUT_ATTN_OFF 2097152  // 2*4096*256

// ---------------- device scratch (no cudaMalloc allowed) ----------------
__device__ float d_Wstack[768 * 256];   // rows 0-255: W_alpha ; 256-511: A=Wg1*Wphi ; 512-767: Bm=Wg1*Wpsi
__device__ float d_Wg2T[256 * 256];     // Wg2T[i][d] = W_g2[d][i]
__device__ float d_Wp2T[64 * 256];      // Wp2T[h][d] = W_p2[d][h]
__device__ float d_CT[64 * 256];        // CT[h][d]   = (Wg1*Wp2)[d][h]
__device__ float d_biash[256];          // b_g1 + Wg1*(b_p2 + b_phi - b_psi)
__device__ float d_nodebuf[8192 * 768]; // per node: [v(256) | qg(256) | kg(256)]
__device__ float d_pos[8192 * 16 * 256];// pos_enc+b_p2 per (point, j, channel)
__device__ int   d_knn[8192 * 16];

// ---------------- packed f32x2 helpers (Blackwell FFMA2) ----------------
__device__ __forceinline__ unsigned long long pack2(float x, float y) {
    unsigned long long r;
    asm("mov.b64 %0, {%1, %2};" : "=l"(r) : "f"(x), "f"(y));
    return r;
}
__device__ __forceinline__ void fma2(unsigned long long& d, unsigned long long a, unsigned long long b) {
    asm("fma.rn.f32x2 %0, %1, %2, %0;" : "+l"(d) : "l"(a), "l"(b));
}
__device__ __forceinline__ float2 unpack2(unsigned long long v) {
    float2 f;
    asm("mov.b64 {%0, %1}, %2;" : "=f"(f.x), "=f"(f.y) : "l"(v));
    return f;
}

// ---------------- fused weight folding (one launch) ----------------
__global__ void k_fold_all(const float* __restrict__ Wg1,
                           const float* __restrict__ Wphi,
                           const float* __restrict__ Wpsi,
                           const float* __restrict__ Walpha,
                           const float* __restrict__ Wg2,
                           const float* __restrict__ Wp2,
                           const float* __restrict__ bg1,
                           const float* __restrict__ bphi,
                           const float* __restrict__ bpsi,
                           const float* __restrict__ bp2) {
    __shared__ float row[256];
    int blk = blockIdx.x, t = threadIdx.x;
    if (blk < 512) {
        int r = blk;
        int src = (r < 256) ? r : r - 256;
        row[t] = Wg1[src * 256 + t];
        __syncthreads();
        const float* W = (r < 256) ? Wphi : Wpsi;
        float acc = 0.f;
        for (int i = 0; i < 256; i++) acc += row[i] * W[i * 256 + t];
        d_Wstack[(256 + r) * 256 + t] = acc;
    } else if (blk < 1088) {
        int r = blk - 512;   // 0..575
        if (r < 256) {
            d_Wstack[r * 256 + t] = Walpha[r * 256 + t];
        } else if (r < 512) {
            int dd = r - 256;
            d_Wg2T[t * 256 + dd] = Wg2[dd * 256 + t];
        } else {
            int idx = (r - 512) * 256 + t;
            int dd = idx >> 6, h = idx & 63;
            d_Wp2T[h * 256 + dd] = Wp2[idx];
        }
    } else if (blk < 1344) {
        int o = blk - 1088;
        for (int i = t; i < 256; i += 256) row[i] = Wg1[o * 256 + i];
        __syncthreads();
        if (t < 64) {
            int hh = t;
            float acc = 0.f;
            for (int tt = 0; tt < 256; tt++) acc += row[tt] * Wp2[tt * 64 + hh];
            d_CT[hh * 256 + o] = acc;
        }
    } else {
        row[t] = bp2[t] + bphi[t] - bpsi[t];
        __syncthreads();
        int wid = t >> 5, lane = t & 31;
        int o = (blk - 1344) * 8 + wid;
        float acc = 0.f;
#pragma unroll
        for (int i = lane; i < 256; i += 32) acc += Wg1[o * 256 + i] * row[i];
#pragma unroll
        for (int off = 16; off > 0; off >>= 1) acc += __shfl_down_sync(0xffffffff, acc, off);
        if (lane == 0) d_biash[o] = bg1[o] + acc;
    }
}

// ---------------- fused knn + node_gemm: independent work co-resident ----------------
// Blocks 0..255: KNN v4 (8 threads/query, float4 tiles, merged top-16).
// Blocks 256..1791: node GEMM, software-pipelined (register prefetch of next k-panel).
__global__ void __launch_bounds__(256) knn_node_kernel(
    const float* __restrict__ xyz,
    const float* __restrict__ feat,
    const float* __restrict__ balpha) {
    __shared__ __align__(16) float pool[8448];
    int blk = blockIdx.x;
    int tid = threadIdx.x;

    if (blk < 256) {
        // ================= KNN path =================
        float4* t4 = (float4*)pool;               // [8][257]
        float*  md = pool;                        // [32][129] (reused after tiles done)
        int*    mi = (int*)(pool + 4160);         // [32][129]

        int q = tid >> 3, part = tid & 7;
        int gq = blk * 32 + q;                    // 256 blocks * 32 = 8192 queries
        int b = gq >> 12;
        float qx = xyz[gq * 3 + 0], qy = xyz[gq * 3 + 1], qz = xyz[gq * 3 + 2];
        float sqq = qx * qx + qy * qy + qz * qz;
        float bd[16];
        int   bi[16];
#pragma unroll
        for (int j = 0; j < 16; j++) { bd[j] = 3.4e38f; bi[j] = 0x7fffffff; }

        for (int t4i = 0; t4i < 2; t4i++) {
            __syncthreads();
#pragma unroll
            for (int r = 0; r < 8; r++) {
                int e = r * 256 + tid;            // 0..2047
                int pp = e >> 8, s = e & 255;
                int g = (b << 12) + (2 * pp + t4i) * 256 + s;
                float x = xyz[g * 3 + 0], y = xyz[g * 3 + 1], z = xyz[g * 3 + 2];
                t4[pp * 257 + s] = make_float4(-2.f * x, -2.f * y, -2.f * z,
                                               x * x + y * y + z * z);
            }
            __syncthreads();
            int mbase = (2 * part + t4i) * 256;
            int pb = part * 257;
#pragma unroll 2
            for (int s = 0; s < 256; s++) {
                float4 v = t4[pb + s];
                float d2 = fmaf(v.x, qx, fmaf(v.y, qy, fmaf(v.z, qz, v.w))) + sqq;
                int m = mbase + s;
                if (d2 < bd[15] || (d2 == bd[15] && m < bi[15])) {
                    bd[15] = d2; bi[15] = m;
#pragma unroll
                    for (int u = 15; u >= 1; --u) {
                        bool sw = bd[u] < bd[u - 1] || (bd[u] == bd[u - 1] && bi[u] < bi[u - 1]);
                        if (sw) {
                            float td = bd[u]; bd[u] = bd[u - 1]; bd[u - 1] = td;
                            int ti = bi[u];  bi[u] = bi[u - 1];  bi[u - 1] = ti;
                        }
                    }
                }
            }
        }
        __syncthreads();   // tiles no longer needed; reuse pool as merge buffer
#pragma unroll
        for (int j = 0; j < 16; j++) {
            md[q * 129 + part * 16 + j] = bd[j];
            mi[q * 129 + part * 16 + j] = bi[j];
        }
        __syncthreads();
        if (part == 0) {
            int p[8] = {0, 16, 32, 48, 64, 80, 96, 112};
#pragma unroll
            for (int r = 0; r < 16; r++) {
                float best = 3.5e38f; int bidx = 0x7fffffff; int bl = 0;
#pragma unroll
                for (int l = 0; l < 8; l++) {
                    int h = p[l];
                    bool valid = h < (l * 16 + 16);
                    float dv = valid ? md[q * 129 + h] : 3.5e38f;
                    int   iv = valid ? mi[q * 129 + h] : 0x7fffffff;
                    if (dv < best || (dv == best && iv < bidx)) { best = dv; bidx = iv; bl = l; }
                }
                p[bl]++;
                d_knn[gq * 16 + r] = bidx;
            }
        }
    } else {
        // ================= node GEMM path (software-pipelined) =================
        float* As = pool;            // [16][68]
        float* Bs = pool + 1088;     // [16][68]
        int idx = blk - 256;         // 0..1535
        int bx = idx % 12, by = idx / 12;
        int tx = tid & 15, ty = tid >> 4;
        int t = tid;
        int o0 = bx * 64, m0 = by * 64;
        unsigned long long acc2[4][2];
#pragma unroll
        for (int i = 0; i < 4; i++) { acc2[i][0] = 0ull; acc2[i][1] = 0ull; }
        int lm = t >> 2, lk = (t & 3) * 4;

        // prologue: load panel 0 into registers
        float4 fa = *(const float4*)&feat[(m0 + lm) * 256 + lk];
        float4 fb = *(const float4*)&d_Wstack[(o0 + lm) * 256 + lk];

        for (int k0 = 0; k0 < 256; k0 += 16) {
            __syncthreads();
            As[(lk + 0) * 68 + lm] = fa.x; As[(lk + 1) * 68 + lm] = fa.y;
            As[(lk + 2) * 68 + lm] = fa.z; As[(lk + 3) * 68 + lm] = fa.w;
            Bs[(lk + 0) * 68 + lm] = fb.x; Bs[(lk + 1) * 68 + lm] = fb.y;
            Bs[(lk + 2) * 68 + lm] = fb.z; Bs[(lk + 3) * 68 + lm] = fb.w;
            __syncthreads();
            // prefetch next panel NOW so latency overlaps the compute below
            if (k0 + 16 < 256) {
                fa = *(const float4*)&feat[(m0 + lm) * 256 + k0 + 16 + lk];
                fb = *(const float4*)&d_Wstack[(o0 + lm) * 256 + k0 + 16 + lk];
            }
#pragma unroll
            for (int kk = 0; kk < 16; kk++) {
                float4 a = *(const float4*)&As[kk * 68 + ty * 4];
                const unsigned long long* bp = (const unsigned long long*)&Bs[kk * 68 + tx * 4];
                unsigned long long b01 = bp[0], b23 = bp[1];
                unsigned long long ax = pack2(a.x, a.x), ay = pack2(a.y, a.y);
                unsigned long long az = pack2(a.z, a.z), aw = pack2(a.w, a.w);
                fma2(acc2[0][0], ax, b01); fma2(acc2[0][1], ax, b23);
                fma2(acc2[1][0], ay, b01); fma2(acc2[1][1], ay, b23);
                fma2(acc2[2][0], az, b01); fma2(acc2[2][1], az, b23);
                fma2(acc2[3][0], aw, b01); fma2(acc2[3][1], aw, b23);
            }
        }
#pragma unroll
        for (int i = 0; i < 4; i++) {
            int m = m0 + ty * 4 + i;
            float2 p0 = unpack2(acc2[i][0]);
            float2 p1 = unpack2(acc2[i][1]);
            float vals[4] = { p0.x, p0.y, p1.x, p1.y };
#pragma unroll
            for (int j = 0; j < 4; j++) {
                int o = o0 + tx * 4 + j;
                float bias = (o < 256) ? balpha[o] : 0.f;
                d_nodebuf[m * 768 + o] = vals[j] + bias;
            }
        }
    }
}

// ---------------- one channel-pass of phase C (R8-exact): accum pos/cc, emit h1 + pos ----------------
__device__ __forceinline__ void phaseC_pass(
    int c, int ph, int g, int b, const float* pe1s, float* h1s,
    const int* idxs, const float* __restrict__ bp2) {
    unsigned long long pp[8], qq[8];
#pragma unroll
    for (int jj = 0; jj < 8; jj++) { pp[jj] = 0ull; qq[jj] = 0ull; }
#pragma unroll 2
    for (int hh = 0; hh < 64; hh++) {
        float w2 = d_Wp2T[hh * 256 + c];
        float wc = d_CT[hh * 256 + c];
        unsigned long long w2p = pack2(w2, w2);
        unsigned long long wcp = pack2(wc, wc);
        const ulonglong2* pr = (const ulonglong2*)&pe1s[hh * 36 + ph * 16];
        ulonglong2 a0 = pr[0], a1 = pr[1], a2 = pr[2], a3 = pr[3];
        fma2(pp[0], w2p, a0.x); fma2(pp[1], w2p, a0.y);
        fma2(pp[2], w2p, a1.x); fma2(pp[3], w2p, a1.y);
        fma2(pp[4], w2p, a2.x); fma2(pp[5], w2p, a2.y);
        fma2(pp[6], w2p, a3.x); fma2(pp[7], w2p, a3.y);
        fma2(qq[0], wcp, a0.x); fma2(qq[1], wcp, a0.y);
        fma2(qq[2], wcp, a1.x); fma2(qq[3], wcp, a1.y);
        fma2(qq[4], wcp, a2.x); fma2(qq[5], wcp, a2.y);
        fma2(qq[6], wcp, a3.x); fma2(qq[7], wcp, a3.y);
    }
    float qg = d_nodebuf[g * 768 + 256 + c];
    float bh = d_biash[c];
    float bp = bp2[c];
    float pos[16], cc[16];
#pragma unroll
    for (int jj = 0; jj < 8; jj++) {
        float2 p = unpack2(pp[jj]); pos[2 * jj] = p.x + bp; pos[2 * jj + 1] = p.y + bp;
        float2 q = unpack2(qq[jj]); cc[2 * jj] = q.x;       cc[2 * jj + 1] = q.y;
    }
#pragma unroll
    for (int j = 0; j < 16; j++) {
        int gm = (b << 12) + idxs[ph * 16 + j];
        float kg = d_nodebuf[gm * 768 + 512 + c];
        h1s[c * 36 + ph * 16 + j] = fmaxf(cc[j] + qg - kg + bh, 0.f);
        d_pos[(g * 16 + j) * 256 + c] = pos[j];
    }
}

// ---------------- main fused attention (R8-exact): 2 points/block, channel-split, occ 3 ----------------
__global__ void __launch_bounds__(256, 3) pt_main_kernel(
    const float* __restrict__ xyz,
    const float* __restrict__ Wp1, const float* __restrict__ bp1,
    const float* __restrict__ bp2, const float* __restrict__ bg2,
    float* __restrict__ out) {
    __shared__ __align__(16) float pe1s[64 * 36];   // [h][jp], jp = p*16+j
    __shared__ __align__(16) float h1s[256 * 36];   // [i][jp]
    __shared__ float nx[32], ny[32], nz[32];
    __shared__ int idxs[32];
    __shared__ float q3[2][3];

    int g0 = blockIdx.x * 2;
    int b = g0 >> 12;
    int tid = threadIdx.x;
    int d2 = tid & 127, ph = tid >> 7;
    int c0 = d2, c1 = d2 + 128;
    int g = g0 + ph;

    if (tid < 32) idxs[tid] = d_knn[g0 * 16 + tid];
    if (tid < 6)  q3[tid / 3][tid % 3] = xyz[(g0 + tid / 3) * 3 + (tid % 3)];
    __syncthreads();
    if (tid < 96) {
        int jp = tid / 3, c = tid % 3;
        float v = xyz[((b << 12) + idxs[jp]) * 3 + c];
        if (c == 0) nx[jp] = v; else if (c == 1) ny[jp] = v; else nz[jp] = v;
    }
    __syncthreads();

    // phase B: pe1[jp][h] = relu(W_p1 rel + b_p1)
#pragma unroll
    for (int r = 0; r < 8; r++) {
        int idx = r * 256 + tid;
        int jp = idx & 31, hh = idx >> 5;
        int p = jp >> 4;
        float rx = q3[p][0] - nx[jp], ry = q3[p][1] - ny[jp], rz = q3[p][2] - nz[jp];
        float v = bp1[hh] + Wp1[hh * 3 + 0] * rx + Wp1[hh * 3 + 1] * ry + Wp1[hh * 3 + 2] * rz;
        pe1s[hh * 36 + jp] = fmaxf(v, 0.f);
    }
    __syncthreads();

    // phase C: two channel passes (register-lean); pos spilled to d_pos
    phaseC_pass(c0, ph, g, b, pe1s, h1s, idxs, bp2);
    phaseC_pass(c1, ph, g, b, pe1s, h1s, idxs, bp2);
    __syncthreads();

    // phase D: attn = W_g2 h1, 2 channels x 16 j of this thread's point
    unsigned long long atA[8], atB[8];
#pragma unroll
    for (int jj = 0; jj < 8; jj++) { atA[jj] = 0ull; atB[jj] = 0ull; }
#pragma unroll 2
    for (int i = 0; i < 256; i++) {
        float wa = d_Wg2T[i * 256 + c0];
        float wb = d_Wg2T[i * 256 + c1];
        unsigned long long wap = pack2(wa, wa), wbp = pack2(wb, wb);
        const ulonglong2* hr = (const ulonglong2*)&h1s[i * 36 + ph * 16];
        ulonglong2 a0 = hr[0], a1 = hr[1], a2 = hr[2], a3 = hr[3];
        fma2(atA[0], wap, a0.x); fma2(atA[1], wap, a0.y);
        fma2(atA[2], wap, a1.x); fma2(atA[3], wap, a1.y);
        fma2(atA[4], wap, a2.x); fma2(atA[5], wap, a2.y);
        fma2(atA[6], wap, a3.x); fma2(atA[7], wap, a3.y);
        fma2(atB[0], wbp, a0.x); fma2(atB[1], wbp, a0.y);
        fma2(atB[2], wbp, a1.x); fma2(atB[3], wbp, a1.y);
        fma2(atB[4], wbp, a2.x); fma2(atB[5], wbp, a2.y);
        fma2(atB[6], wbp, a3.x); fma2(atB[7], wbp, a3.y);
    }

    float bgA = bg2[c0], bgB = bg2[c1];
    float attnA[16], attnB[16];
#pragma unroll
    for (int jj = 0; jj < 8; jj++) {
        float2 aa = unpack2(atA[jj]); attnA[2 * jj] = aa.x; attnA[2 * jj + 1] = aa.y;
        float2 ab = unpack2(atB[jj]); attnB[2 * jj] = ab.x; attnB[2 * jj + 1] = ab.y;
    }
    float mxA = -3.4e38f, mxB = -3.4e38f;
#pragma unroll
    for (int j = 0; j < 16; j++) {
        attnA[j] = (attnA[j] + bgA) * 0.0625f; mxA = fmaxf(mxA, attnA[j]);
        attnB[j] = (attnB[j] + bgB) * 0.0625f; mxB = fmaxf(mxB, attnB[j]);
    }
    float sumA = 0.f, sumB = 0.f;
#pragma unroll
    for (int j = 0; j < 16; j++) {
        attnA[j] = expf(attnA[j] - mxA); sumA += attnA[j];
        attnB[j] = expf(attnB[j] - mxB); sumB += attnB[j];
    }
    float invA = 1.f / sumA, invB = 1.f / sumB;
    float accA = 0.f, accB = 0.f;
#pragma unroll
    for (int j = 0; j < 16; j++) {
        float wA = attnA[j] * invA, wB = attnB[j] * invB;
        int gm = (b << 12) + idxs[ph * 16 + j];
        float vA = d_nodebuf[gm * 768 + c0];
        float vB = d_nodebuf[gm * 768 + c1];
        float pA = d_pos[(g * 16 + j) * 256 + c0];
        float pB = d_pos[(g * 16 + j) * 256 + c1];
        accA += wA * (vA + pA);
        accB += wB * (vB + pB);
        out[OUT_ATTN_OFF + (g * 16 + j) * 256 + c0] = wA;
        out[OUT_ATTN_OFF + (g * 16 + j) * 256 + c1] = wB;
    }
    out[g * 256 + c0] = accA;
    out[g * 256 + c1] = accB;
}

// ---------------- launch ----------------
extern "C" void kernel_launch(void* const* d_in, const int* in_sizes, int n_in,
                              void* d_out, int out_size) {
    const float* feat   = (const float*)d_in[0];
    const float* xyz    = (const float*)d_in[1];
    const float* Wphi   = (const float*)d_in[2];
    const float* bphi   = (const float*)d_in[3];
    const float* Wpsi   = (const float*)d_in[4];
    const float* bpsi   = (const float*)d_in[5];
    const float* Walpha = (const float*)d_in[6];
    const float* balpha = (const float*)d_in[7];
    const float* Wg1    = (const float*)d_in[8];
    const float* bg1    = (const float*)d_in[9];
    const float* Wg2    = (const float*)d_in[10];
    const float* bg2    = (const float*)d_in[11];
    const float* Wp1    = (const float*)d_in[12];
    const float* bp1    = (const float*)d_in[13];
    const float* Wp2    = (const float*)d_in[14];
    const float* bp2    = (const float*)d_in[15];
    float* out = (float*)d_out;

    k_fold_all<<<1376, 256>>>(Wg1, Wphi, Wpsi, Walpha, Wg2, Wp2, bg1, bphi, bpsi, bp2);
    knn_node_kernel<<<1792, 256>>>(xyz, feat, balpha);
    pt_main_kernel<<<4096, 256>>>(xyz, Wp1, bp1, bp2, bg2, out);
}

// round 15
// speedup vs baseline: 1.0365x; 1.0365x over previous
#include <cuda_runtime.h>
#include <math.h>

// Problem constants: B=2, N=4096, D=256, H=64, K=16
#define OUT_ATTN_OFF 2097152  // 2*4096*256

// ---------------- device scratch (no cudaMalloc allowed) ----------------
__device__ float d_Wstack[768 * 256];   // rows 0-255: W_alpha ; 256-511: A=Wg1*Wphi ; 512-767: Bm=Wg1*Wpsi
__device__ float d_Wg2T[256 * 256];     // Wg2T[i][d] = W_g2[d][i]
__device__ float d_Wp2T[64 * 256];      // Wp2T[h][d] = W_p2[d][h]
__device__ float d_CT[64 * 256];        // CT[h][d]   = (Wg1*Wp2)[d][h]
__device__ float d_biash[256];          // b_g1 + Wg1*(b_p2 + b_phi - b_psi)
__device__ float d_nodebuf[8192 * 768]; // per node: [v(256) | qg(256) | kg(256)]
__device__ float d_pos[8192 * 16 * 256];// pos_enc+b_p2 per (point, j, channel)
__device__ int   d_knn[8192 * 16];

// ---------------- packed f32x2 helpers (Blackwell FFMA2) ----------------
__device__ __forceinline__ unsigned long long pack2(float x, float y) {
    unsigned long long r;
    asm("mov.b64 %0, {%1, %2};" : "=l"(r) : "f"(x), "f"(y));
    return r;
}
__device__ __forceinline__ void fma2(unsigned long long& d, unsigned long long a, unsigned long long b) {
    asm("fma.rn.f32x2 %0, %1, %2, %0;" : "+l"(d) : "l"(a), "l"(b));
}
__device__ __forceinline__ float2 unpack2(unsigned long long v) {
    float2 f;
    asm("mov.b64 {%0, %1}, %2;" : "=f"(f.x), "=f"(f.y) : "l"(v));
    return f;
}

// ---------------- fused weight folding (one launch) ----------------
__global__ void k_fold_all(const float* __restrict__ Wg1,
                           const float* __restrict__ Wphi,
                           const float* __restrict__ Wpsi,
                           const float* __restrict__ Walpha,
                           const float* __restrict__ Wg2,
                           const float* __restrict__ Wp2,
                           const float* __restrict__ bg1,
                           const float* __restrict__ bphi,
                           const float* __restrict__ bpsi,
                           const float* __restrict__ bp2) {
    __shared__ float row[256];
    int blk = blockIdx.x, t = threadIdx.x;
    if (blk < 512) {
        int r = blk;
        int src = (r < 256) ? r : r - 256;
        row[t] = Wg1[src * 256 + t];
        __syncthreads();
        const float* W = (r < 256) ? Wphi : Wpsi;
        float acc = 0.f;
        for (int i = 0; i < 256; i++) acc += row[i] * W[i * 256 + t];
        d_Wstack[(256 + r) * 256 + t] = acc;
    } else if (blk < 1088) {
        int r = blk - 512;   // 0..575
        if (r < 256) {
            d_Wstack[r * 256 + t] = Walpha[r * 256 + t];
        } else if (r < 512) {
            int dd = r - 256;
            d_Wg2T[t * 256 + dd] = Wg2[dd * 256 + t];
        } else {
            int idx = (r - 512) * 256 + t;
            int dd = idx >> 6, h = idx & 63;
            d_Wp2T[h * 256 + dd] = Wp2[idx];
        }
    } else if (blk < 1344) {
        int o = blk - 1088;
        for (int i = t; i < 256; i += 256) row[i] = Wg1[o * 256 + i];
        __syncthreads();
        if (t < 64) {
            int hh = t;
            float acc = 0.f;
            for (int tt = 0; tt < 256; tt++) acc += row[tt] * Wp2[tt * 64 + hh];
            d_CT[hh * 256 + o] = acc;
        }
    } else {
        row[t] = bp2[t] + bphi[t] - bpsi[t];
        __syncthreads();
        int wid = t >> 5, lane = t & 31;
        int o = (blk - 1344) * 8 + wid;
        float acc = 0.f;
#pragma unroll
        for (int i = lane; i < 256; i += 32) acc += Wg1[o * 256 + i] * row[i];
#pragma unroll
        for (int off = 16; off > 0; off >>= 1) acc += __shfl_down_sync(0xffffffff, acc, off);
        if (lane == 0) d_biash[o] = bg1[o] + acc;
    }
}

// ---------------- fused knn + node_gemm ----------------
// Blocks 0..255: KNN v5 — u64 (d2,idx) keys, one setp.u64 per compare.
// Blocks 256..1791: node GEMM — double-buffered smem panels (1 barrier/panel).
__global__ void __launch_bounds__(256) knn_node_kernel(
    const float* __restrict__ xyz,
    const float* __restrict__ feat,
    const float* __restrict__ balpha) {
    __shared__ __align__(16) float pool[8448];
    int blk = blockIdx.x;
    int tid = threadIdx.x;

    if (blk < 256) {
        // ================= KNN path =================
        float4* t4 = (float4*)pool;                       // [8][257]
        unsigned long long* mk = (unsigned long long*)pool; // [32][129] keys (reused)

        int q = tid >> 3, part = tid & 7;
        int gq = blk * 32 + q;                    // 256 blocks * 32 = 8192 queries
        int b = gq >> 12;
        float qx = xyz[gq * 3 + 0], qy = xyz[gq * 3 + 1], qz = xyz[gq * 3 + 2];
        float sqq = qx * qx + qy * qy + qz * qz;
        unsigned long long bk[16];
#pragma unroll
        for (int j = 0; j < 16; j++) bk[j] = 0xffffffffffffffffull;

        for (int t4i = 0; t4i < 2; t4i++) {
            __syncthreads();
#pragma unroll
            for (int r = 0; r < 8; r++) {
                int e = r * 256 + tid;            // 0..2047
                int pp = e >> 8, s = e & 255;
                int g = (b << 12) + (2 * pp + t4i) * 256 + s;
                float x = xyz[g * 3 + 0], y = xyz[g * 3 + 1], z = xyz[g * 3 + 2];
                t4[pp * 257 + s] = make_float4(-2.f * x, -2.f * y, -2.f * z,
                                               x * x + y * y + z * z);
            }
            __syncthreads();
            int mbase = (2 * part + t4i) * 256;
            int pb = part * 257;
#pragma unroll 2
            for (int s = 0; s < 256; s++) {
                float4 v = t4[pb + s];
                float d2 = fmaf(v.x, qx, fmaf(v.y, qy, fmaf(v.z, qz, v.w))) + sqq;
                unsigned int ub = __float_as_uint(d2);
                ub = ((int)ub < 0) ? ~ub : (ub | 0x80000000u);  // sign-monotone map
                unsigned long long key =
                    ((unsigned long long)ub << 32) | (unsigned int)(mbase + s);
                if (key < bk[15]) {
                    bk[15] = key;
#pragma unroll
                    for (int u = 15; u >= 1; --u) {
                        unsigned long long a = bk[u - 1], c = bk[u];
                        bool sw = c < a;
                        bk[u - 1] = sw ? c : a;
                        bk[u]     = sw ? a : c;
                    }
                }
            }
        }
        __syncthreads();   // tiles no longer needed; reuse pool as key buffer
#pragma unroll
        for (int j = 0; j < 16; j++)
            mk[q * 129 + part * 16 + j] = bk[j];
        __syncthreads();
        if (part == 0) {
            int p[8] = {0, 16, 32, 48, 64, 80, 96, 112};
#pragma unroll
            for (int r = 0; r < 16; r++) {
                unsigned long long best = 0xffffffffffffffffull;
                int bl = 0;
#pragma unroll
                for (int l = 0; l < 8; l++) {
                    int h = p[l];
                    bool valid = h < (l * 16 + 16);
                    unsigned long long kv = valid ? mk[q * 129 + h] : 0xffffffffffffffffull;
                    if (kv < best) { best = kv; bl = l; }
                }
                p[bl]++;
                d_knn[gq * 16 + r] = (int)(best & 0xffffffffu);
            }
        }
    } else {
        // ================= node GEMM path (double-buffered) =================
        // two buffers: bufN = pool + N*2176 ; each = As[16][68] + Bs[16][68]
        int idx = blk - 256;         // 0..1535
        int bx = idx % 12, by = idx / 12;
        int tx = tid & 15, ty = tid >> 4;
        int t = tid;
        int o0 = bx * 64, m0 = by * 64;
        unsigned long long acc2[4][2];
#pragma unroll
        for (int i = 0; i < 4; i++) { acc2[i][0] = 0ull; acc2[i][1] = 0ull; }
        int lm = t >> 2, lk = (t & 3) * 4;

        // prologue: panel 0 -> buf0
        float4 fa = *(const float4*)&feat[(m0 + lm) * 256 + lk];
        float4 fb = *(const float4*)&d_Wstack[(o0 + lm) * 256 + lk];
        {
            float* As = pool;
            float* Bs = pool + 1088;
            As[(lk + 0) * 68 + lm] = fa.x; As[(lk + 1) * 68 + lm] = fa.y;
            As[(lk + 2) * 68 + lm] = fa.z; As[(lk + 3) * 68 + lm] = fa.w;
            Bs[(lk + 0) * 68 + lm] = fb.x; Bs[(lk + 1) * 68 + lm] = fb.y;
            Bs[(lk + 2) * 68 + lm] = fb.z; Bs[(lk + 3) * 68 + lm] = fb.w;
        }
        __syncthreads();

        for (int k0 = 0; k0 < 256; k0 += 16) {
            int cur = (k0 >> 4) & 1;
            float* As = pool + cur * 2176;
            float* Bs = As + 1088;
            bool more = (k0 + 16 < 256);
            if (more) {
                fa = *(const float4*)&feat[(m0 + lm) * 256 + k0 + 16 + lk];
                fb = *(const float4*)&d_Wstack[(o0 + lm) * 256 + k0 + 16 + lk];
            }
#pragma unroll
            for (int kk = 0; kk < 16; kk++) {
                float4 a = *(const float4*)&As[kk * 68 + ty * 4];
                const unsigned long long* bp = (const unsigned long long*)&Bs[kk * 68 + tx * 4];
                unsigned long long b01 = bp[0], b23 = bp[1];
                unsigned long long ax = pack2(a.x, a.x), ay = pack2(a.y, a.y);
                unsigned long long az = pack2(a.z, a.z), aw = pack2(a.w, a.w);
                fma2(acc2[0][0], ax, b01); fma2(acc2[0][1], ax, b23);
                fma2(acc2[1][0], ay, b01); fma2(acc2[1][1], ay, b23);
                fma2(acc2[2][0], az, b01); fma2(acc2[2][1], az, b23);
                fma2(acc2[3][0], aw, b01); fma2(acc2[3][1], aw, b23);
            }
            if (more) {
                float* As2 = pool + (1 - cur) * 2176;
                float* Bs2 = As2 + 1088;
                As2[(lk + 0) * 68 + lm] = fa.x; As2[(lk + 1) * 68 + lm] = fa.y;
                As2[(lk + 2) * 68 + lm] = fa.z; As2[(lk + 3) * 68 + lm] = fa.w;
                Bs2[(lk + 0) * 68 + lm] = fb.x; Bs2[(lk + 1) * 68 + lm] = fb.y;
                Bs2[(lk + 2) * 68 + lm] = fb.z; Bs2[(lk + 3) * 68 + lm] = fb.w;
                __syncthreads();
            }
        }
#pragma unroll
        for (int i = 0; i < 4; i++) {
            int m = m0 + ty * 4 + i;
            float2 p0 = unpack2(acc2[i][0]);
            float2 p1 = unpack2(acc2[i][1]);
            float vals[4] = { p0.x, p0.y, p1.x, p1.y };
#pragma unroll
            for (int j = 0; j < 4; j++) {
                int o = o0 + tx * 4 + j;
                float bias = (o < 256) ? balpha[o] : 0.f;
                d_nodebuf[m * 768 + o] = vals[j] + bias;
            }
        }
    }
}

// ---------------- one channel-pass of phase C (R8-exact): accum pos/cc, emit h1 + pos ----------------
__device__ __forceinline__ void phaseC_pass(
    int c, int ph, int g, int b, const float* pe1s, float* h1s,
    const int* idxs, const float* __restrict__ bp2) {
    unsigned long long pp[8], qq[8];
#pragma unroll
    for (int jj = 0; jj < 8; jj++) { pp[jj] = 0ull; qq[jj] = 0ull; }
#pragma unroll 2
    for (int hh = 0; hh < 64; hh++) {
        float w2 = d_Wp2T[hh * 256 + c];
        float wc = d_CT[hh * 256 + c];
        unsigned long long w2p = pack2(w2, w2);
        unsigned long long wcp = pack2(wc, wc);
        const ulonglong2* pr = (const ulonglong2*)&pe1s[hh * 36 + ph * 16];
        ulonglong2 a0 = pr[0], a1 = pr[1], a2 = pr[2], a3 = pr[3];
        fma2(pp[0], w2p, a0.x); fma2(pp[1], w2p, a0.y);
        fma2(pp[2], w2p, a1.x); fma2(pp[3], w2p, a1.y);
        fma2(pp[4], w2p, a2.x); fma2(pp[5], w2p, a2.y);
        fma2(pp[6], w2p, a3.x); fma2(pp[7], w2p, a3.y);
        fma2(qq[0], wcp, a0.x); fma2(qq[1], wcp, a0.y);
        fma2(qq[2], wcp, a1.x); fma2(qq[3], wcp, a1.y);
        fma2(qq[4], wcp, a2.x); fma2(qq[5], wcp, a2.y);
        fma2(qq[6], wcp, a3.x); fma2(qq[7], wcp, a3.y);
    }
    float qg = d_nodebuf[g * 768 + 256 + c];
    float bh = d_biash[c];
    float bp = bp2[c];
    float pos[16], cc[16];
#pragma unroll
    for (int jj = 0; jj < 8; jj++) {
        float2 p = unpack2(pp[jj]); pos[2 * jj] = p.x + bp; pos[2 * jj + 1] = p.y + bp;
        float2 q = unpack2(qq[jj]); cc[2 * jj] = q.x;       cc[2 * jj + 1] = q.y;
    }
#pragma unroll
    for (int j = 0; j < 16; j++) {
        int gm = (b << 12) + idxs[ph * 16 + j];
        float kg = d_nodebuf[gm * 768 + 512 + c];
        h1s[c * 36 + ph * 16 + j] = fmaxf(cc[j] + qg - kg + bh, 0.f);
        d_pos[(g * 16 + j) * 256 + c] = pos[j];
    }
}

// ---------------- main fused attention (R8-exact): 2 points/block, channel-split, occ 3 ----------------
__global__ void __launch_bounds__(256, 3) pt_main_kernel(
    const float* __restrict__ xyz,
    const float* __restrict__ Wp1, const float* __restrict__ bp1,
    const float* __restrict__ bp2, const float* __restrict__ bg2,
    float* __restrict__ out) {
    __shared__ __align__(16) float pe1s[64 * 36];   // [h][jp], jp = p*16+j
    __shared__ __align__(16) float h1s[256 * 36];   // [i][jp]
    __shared__ float nx[32], ny[32], nz[32];
    __shared__ int idxs[32];
    __shared__ float q3[2][3];

    int g0 = blockIdx.x * 2;
    int b = g0 >> 12;
    int tid = threadIdx.x;
    int d2 = tid & 127, ph = tid >> 7;
    int c0 = d2, c1 = d2 + 128;
    int g = g0 + ph;

    if (tid < 32) idxs[tid] = d_knn[g0 * 16 + tid];
    if (tid < 6)  q3[tid / 3][tid % 3] = xyz[(g0 + tid / 3) * 3 + (tid % 3)];
    __syncthreads();
    if (tid < 96) {
        int jp = tid / 3, c = tid % 3;
        float v = xyz[((b << 12) + idxs[jp]) * 3 + c];
        if (c == 0) nx[jp] = v; else if (c == 1) ny[jp] = v; else nz[jp] = v;
    }
    __syncthreads();

    // phase B: pe1[jp][h] = relu(W_p1 rel + b_p1)
#pragma unroll
    for (int r = 0; r < 8; r++) {
        int idx = r * 256 + tid;
        int jp = idx & 31, hh = idx >> 5;
        int p = jp >> 4;
        float rx = q3[p][0] - nx[jp], ry = q3[p][1] - ny[jp], rz = q3[p][2] - nz[jp];
        float v = bp1[hh] + Wp1[hh * 3 + 0] * rx + Wp1[hh * 3 + 1] * ry + Wp1[hh * 3 + 2] * rz;
        pe1s[hh * 36 + jp] = fmaxf(v, 0.f);
    }
    __syncthreads();

    // phase C: two channel passes (register-lean); pos spilled to d_pos
    phaseC_pass(c0, ph, g, b, pe1s, h1s, idxs, bp2);
    phaseC_pass(c1, ph, g, b, pe1s, h1s, idxs, bp2);
    __syncthreads();

    // phase D: attn = W_g2 h1, 2 channels x 16 j of this thread's point
    unsigned long long atA[8], atB[8];
#pragma unroll
    for (int jj = 0; jj < 8; jj++) { atA[jj] = 0ull; atB[jj] = 0ull; }
#pragma unroll 2
    for (int i = 0; i < 256; i++) {
        float wa = d_Wg2T[i * 256 + c0];
        float wb = d_Wg2T[i * 256 + c1];
        unsigned long long wap = pack2(wa, wa), wbp = pack2(wb, wb);
        const ulonglong2* hr = (const ulonglong2*)&h1s[i * 36 + ph * 16];
        ulonglong2 a0 = hr[0], a1 = hr[1], a2 = hr[2], a3 = hr[3];
        fma2(atA[0], wap, a0.x); fma2(atA[1], wap, a0.y);
        fma2(atA[2], wap, a1.x); fma2(atA[3], wap, a1.y);
        fma2(atA[4], wap, a2.x); fma2(atA[5], wap, a2.y);
        fma2(atA[6], wap, a3.x); fma2(atA[7], wap, a3.y);
        fma2(atB[0], wbp, a0.x); fma2(atB[1], wbp, a0.y);
        fma2(atB[2], wbp, a1.x); fma2(atB[3], wbp, a1.y);
        fma2(atB[4], wbp, a2.x); fma2(atB[5], wbp, a2.y);
        fma2(atB[6], wbp, a3.x); fma2(atB[7], wbp, a3.y);
    }

    float bgA = bg2[c0], bgB = bg2[c1];
    float attnA[16], attnB[16];
#pragma unroll
    for (int jj = 0; jj < 8; jj++) {
        float2 aa = unpack2(atA[jj]); attnA[2 * jj] = aa.x; attnA[2 * jj + 1] = aa.y;
        float2 ab = unpack2(atB[jj]); attnB[2 * jj] = ab.x; attnB[2 * jj + 1] = ab.y;
    }
    float mxA = -3.4e38f, mxB = -3.4e38f;
#pragma unroll
    for (int j = 0; j < 16; j++) {
        attnA[j] = (attnA[j] + bgA) * 0.0625f; mxA = fmaxf(mxA, attnA[j]);
        attnB[j] = (attnB[j] + bgB) * 0.0625f; mxB = fmaxf(mxB, attnB[j]);
    }
    float sumA = 0.f, sumB = 0.f;
#pragma unroll
    for (int j = 0; j < 16; j++) {
        attnA[j] = expf(attnA[j] - mxA); sumA += attnA[j];
        attnB[j] = expf(attnB[j] - mxB); sumB += attnB[j];
    }
    float invA = 1.f / sumA, invB = 1.f / sumB;
    float accA = 0.f, accB = 0.f;
#pragma unroll
    for (int j = 0; j < 16; j++) {
        float wA = attnA[j] * invA, wB = attnB[j] * invB;
        int gm = (b << 12) + idxs[ph * 16 + j];
        float vA = d_nodebuf[gm * 768 + c0];
        float vB = d_nodebuf[gm * 768 + c1];
        float pA = d_pos[(g * 16 + j) * 256 + c0];
        float pB = d_pos[(g * 16 + j) * 256 + c1];
        accA += wA * (vA + pA);
        accB += wB * (vB + pB);
        out[OUT_ATTN_OFF + (g * 16 + j) * 256 + c0] = wA;
        out[OUT_ATTN_OFF + (g * 16 + j) * 256 + c1] = wB;
    }
    out[g * 256 + c0] = accA;
    out[g * 256 + c1] = accB;
}

// ---------------- launch ----------------
extern "C" void kernel_launch(void* const* d_in, const int* in_sizes, int n_in,
                              void* d_out, int out_size) {
    const float* feat   = (const float*)d_in[0];
    const float* xyz    = (const float*)d_in[1];
    const float* Wphi   = (const float*)d_in[2];
    const float* bphi   = (const float*)d_in[3];
    const float* Wpsi   = (const float*)d_in[4];
    const float* bpsi   = (const float*)d_in[5];
    const float* Walpha = (const float*)d_in[6];
    const float* balpha = (const float*)d_in[7];
    const float* Wg1    = (const float*)d_in[8];
    const float* bg1    = (const float*)d_in[9];
    const float* Wg2    = (const float*)d_in[10];
    const float* bg2    = (const float*)d_in[11];
    const float* Wp1    = (const float*)d_in[12];
    const float* bp1    = (const float*)d_in[13];
    const float* Wp2    = (const float*)d_in[14];
    const float* bp2    = (const float*)d_in[15];
    float* out = (float*)d_out;

    k_fold_all<<<1376, 256>>>(Wg1, Wphi, Wpsi, Walpha, Wg2, Wp2, bg1, bphi, bpsi, bp2);
    knn_node_kernel<<<1792, 256>>>(xyz, feat, balpha);
    pt_main_kernel<<<4096, 256>>>(xyz, Wp1, bp1, bp2, bg2, out);
}

// round 16
// speedup vs baseline: 1.1489x; 1.1084x over previous
#include <cuda_runtime.h>
#include <math.h>
#include <mma.h>

// Problem constants: B=2, N=4096, D=256, H=64, K=16
#define OUT_ATTN_OFF 2097152  // 2*4096*256

// ---------------- device scratch (no cudaMalloc allowed) ----------------
__device__ float d_Wstack[768 * 256];   // rows 0-255: W_alpha ; 256-511: A=Wg1*Wphi ; 512-767: Bm=Wg1*Wpsi
__device__ float d_Wg2T[256 * 256];     // Wg2T[i][d] = W_g2[d][i]
__device__ float d_Wp2T[64 * 256];      // Wp2T[h][d] = W_p2[d][h]
__device__ float d_CT[64 * 256];        // CT[h][d]   = (Wg1*Wp2)[d][h]
__device__ float d_biash[256];          // b_g1 + Wg1*(b_p2 + b_phi - b_psi)
__device__ float d_nodebuf[8192 * 768]; // per node: [v(256) | qg(256) | kg(256)]
__device__ float d_pos[8192 * 16 * 256];// pos_enc+b_p2 per (point, j, channel)
__device__ int   d_knn[8192 * 16];

// ---------------- packed f32x2 helpers (Blackwell FFMA2) ----------------
__device__ __forceinline__ unsigned long long pack2(float x, float y) {
    unsigned long long r;
    asm("mov.b64 %0, {%1, %2};" : "=l"(r) : "f"(x), "f"(y));
    return r;
}
__device__ __forceinline__ void fma2(unsigned long long& d, unsigned long long a, unsigned long long b) {
    asm("fma.rn.f32x2 %0, %1, %2, %0;" : "+l"(d) : "l"(a), "l"(b));
}
__device__ __forceinline__ float2 unpack2(unsigned long long v) {
    float2 f;
    asm("mov.b64 {%0, %1}, %2;" : "=f"(f.x), "=f"(f.y) : "l"(v));
    return f;
}

// ---------------- fused weight folding (one launch) ----------------
__global__ void k_fold_all(const float* __restrict__ Wg1,
                           const float* __restrict__ Wphi,
                           const float* __restrict__ Wpsi,
                           const float* __restrict__ Walpha,
                           const float* __restrict__ Wg2,
                           const float* __restrict__ Wp2,
                           const float* __restrict__ bg1,
                           const float* __restrict__ bphi,
                           const float* __restrict__ bpsi,
                           const float* __restrict__ bp2) {
    __shared__ float row[256];
    int blk = blockIdx.x, t = threadIdx.x;
    if (blk < 512) {
        int r = blk;
        int src = (r < 256) ? r : r - 256;
        row[t] = Wg1[src * 256 + t];
        __syncthreads();
        const float* W = (r < 256) ? Wphi : Wpsi;
        float acc = 0.f;
        for (int i = 0; i < 256; i++) acc += row[i] * W[i * 256 + t];
        d_Wstack[(256 + r) * 256 + t] = acc;
    } else if (blk < 1088) {
        int r = blk - 512;   // 0..575
        if (r < 256) {
            d_Wstack[r * 256 + t] = Walpha[r * 256 + t];
        } else if (r < 512) {
            int dd = r - 256;
            d_Wg2T[t * 256 + dd] = Wg2[dd * 256 + t];
        } else {
            int idx = (r - 512) * 256 + t;
            int dd = idx >> 6, h = idx & 63;
            d_Wp2T[h * 256 + dd] = Wp2[idx];
        }
    } else if (blk < 1344) {
        int o = blk - 1088;
        for (int i = t; i < 256; i += 256) row[i] = Wg1[o * 256 + i];
        __syncthreads();
        if (t < 64) {
            int hh = t;
            float acc = 0.f;
            for (int tt = 0; tt < 256; tt++) acc += row[tt] * Wp2[tt * 64 + hh];
            d_CT[hh * 256 + o] = acc;
        }
    } else {
        row[t] = bp2[t] + bphi[t] - bpsi[t];
        __syncthreads();
        int wid = t >> 5, lane = t & 31;
        int o = (blk - 1344) * 8 + wid;
        float acc = 0.f;
#pragma unroll
        for (int i = lane; i < 256; i += 32) acc += Wg1[o * 256 + i] * row[i];
#pragma unroll
        for (int off = 16; off > 0; off >>= 1) acc += __shfl_down_sync(0xffffffff, acc, off);
        if (lane == 0) d_biash[o] = bg1[o] + acc;
    }
}

// ---------------- fused knn + node_gemm ----------------
// Blocks 0..255: KNN v5 — u64 (d2,idx) keys, one setp.u64 per compare.
// Blocks 256..1791: node GEMM — double-buffered smem panels (1 barrier/panel).
__global__ void __launch_bounds__(256) knn_node_kernel(
    const float* __restrict__ xyz,
    const float* __restrict__ feat,
    const float* __restrict__ balpha) {
    __shared__ __align__(16) float pool[8448];
    int blk = blockIdx.x;
    int tid = threadIdx.x;

    if (blk < 256) {
        // ================= KNN path =================
        float4* t4 = (float4*)pool;                       // [8][257]
        unsigned long long* mk = (unsigned long long*)pool; // [32][129] keys (reused)

        int q = tid >> 3, part = tid & 7;
        int gq = blk * 32 + q;                    // 256 blocks * 32 = 8192 queries
        int b = gq >> 12;
        float qx = xyz[gq * 3 + 0], qy = xyz[gq * 3 + 1], qz = xyz[gq * 3 + 2];
        float sqq = qx * qx + qy * qy + qz * qz;
        unsigned long long bk[16];
#pragma unroll
        for (int j = 0; j < 16; j++) bk[j] = 0xffffffffffffffffull;

        for (int t4i = 0; t4i < 2; t4i++) {
            __syncthreads();
#pragma unroll
            for (int r = 0; r < 8; r++) {
                int e = r * 256 + tid;            // 0..2047
                int pp = e >> 8, s = e & 255;
                int g = (b << 12) + (2 * pp + t4i) * 256 + s;
                float x = xyz[g * 3 + 0], y = xyz[g * 3 + 1], z = xyz[g * 3 + 2];
                t4[pp * 257 + s] = make_float4(-2.f * x, -2.f * y, -2.f * z,
                                               x * x + y * y + z * z);
            }
            __syncthreads();
            int mbase = (2 * part + t4i) * 256;
            int pb = part * 257;
#pragma unroll 2
            for (int s = 0; s < 256; s++) {
                float4 v = t4[pb + s];
                float d2 = fmaf(v.x, qx, fmaf(v.y, qy, fmaf(v.z, qz, v.w))) + sqq;
                unsigned int ub = __float_as_uint(d2);
                ub = ((int)ub < 0) ? ~ub : (ub | 0x80000000u);  // sign-monotone map
                unsigned long long key =
                    ((unsigned long long)ub << 32) | (unsigned int)(mbase + s);
                if (key < bk[15]) {
                    bk[15] = key;
#pragma unroll
                    for (int u = 15; u >= 1; --u) {
                        unsigned long long a = bk[u - 1], c = bk[u];
                        bool sw = c < a;
                        bk[u - 1] = sw ? c : a;
                        bk[u]     = sw ? a : c;
                    }
                }
            }
        }
        __syncthreads();   // tiles no longer needed; reuse pool as key buffer
#pragma unroll
        for (int j = 0; j < 16; j++)
            mk[q * 129 + part * 16 + j] = bk[j];
        __syncthreads();
        if (part == 0) {
            int p[8] = {0, 16, 32, 48, 64, 80, 96, 112};
#pragma unroll
            for (int r = 0; r < 16; r++) {
                unsigned long long best = 0xffffffffffffffffull;
                int bl = 0;
#pragma unroll
                for (int l = 0; l < 8; l++) {
                    int h = p[l];
                    bool valid = h < (l * 16 + 16);
                    unsigned long long kv = valid ? mk[q * 129 + h] : 0xffffffffffffffffull;
                    if (kv < best) { best = kv; bl = l; }
                }
                p[bl]++;
                d_knn[gq * 16 + r] = (int)(best & 0xffffffffu);
            }
        }
    } else {
        // ================= node GEMM path (double-buffered) =================
        int idx = blk - 256;         // 0..1535
        int bx = idx % 12, by = idx / 12;
        int tx = tid & 15, ty = tid >> 4;
        int t = tid;
        int o0 = bx * 64, m0 = by * 64;
        unsigned long long acc2[4][2];
#pragma unroll
        for (int i = 0; i < 4; i++) { acc2[i][0] = 0ull; acc2[i][1] = 0ull; }
        int lm = t >> 2, lk = (t & 3) * 4;

        float4 fa = *(const float4*)&feat[(m0 + lm) * 256 + lk];
        float4 fb = *(const float4*)&d_Wstack[(o0 + lm) * 256 + lk];
        {
            float* As = pool;
            float* Bs = pool + 1088;
            As[(lk + 0) * 68 + lm] = fa.x; As[(lk + 1) * 68 + lm] = fa.y;
            As[(lk + 2) * 68 + lm] = fa.z; As[(lk + 3) * 68 + lm] = fa.w;
            Bs[(lk + 0) * 68 + lm] = fb.x; Bs[(lk + 1) * 68 + lm] = fb.y;
            Bs[(lk + 2) * 68 + lm] = fb.z; Bs[(lk + 3) * 68 + lm] = fb.w;
        }
        __syncthreads();

        for (int k0 = 0; k0 < 256; k0 += 16) {
            int cur = (k0 >> 4) & 1;
            float* As = pool + cur * 2176;
            float* Bs = As + 1088;
            bool more = (k0 + 16 < 256);
            if (more) {
                fa = *(const float4*)&feat[(m0 + lm) * 256 + k0 + 16 + lk];
                fb = *(const float4*)&d_Wstack[(o0 + lm) * 256 + k0 + 16 + lk];
            }
#pragma unroll
            for (int kk = 0; kk < 16; kk++) {
                float4 a = *(const float4*)&As[kk * 68 + ty * 4];
                const unsigned long long* bp = (const unsigned long long*)&Bs[kk * 68 + tx * 4];
                unsigned long long b01 = bp[0], b23 = bp[1];
                unsigned long long ax = pack2(a.x, a.x), ay = pack2(a.y, a.y);
                unsigned long long az = pack2(a.z, a.z), aw = pack2(a.w, a.w);
                fma2(acc2[0][0], ax, b01); fma2(acc2[0][1], ax, b23);
                fma2(acc2[1][0], ay, b01); fma2(acc2[1][1], ay, b23);
                fma2(acc2[2][0], az, b01); fma2(acc2[2][1], az, b23);
                fma2(acc2[3][0], aw, b01); fma2(acc2[3][1], aw, b23);
            }
            if (more) {
                float* As2 = pool + (1 - cur) * 2176;
                float* Bs2 = As2 + 1088;
                As2[(lk + 0) * 68 + lm] = fa.x; As2[(lk + 1) * 68 + lm] = fa.y;
                As2[(lk + 2) * 68 + lm] = fa.z; As2[(lk + 3) * 68 + lm] = fa.w;
                Bs2[(lk + 0) * 68 + lm] = fb.x; Bs2[(lk + 1) * 68 + lm] = fb.y;
                Bs2[(lk + 2) * 68 + lm] = fb.z; Bs2[(lk + 3) * 68 + lm] = fb.w;
                __syncthreads();
            }
        }
#pragma unroll
        for (int i = 0; i < 4; i++) {
            int m = m0 + ty * 4 + i;
            float2 p0 = unpack2(acc2[i][0]);
            float2 p1 = unpack2(acc2[i][1]);
            float vals[4] = { p0.x, p0.y, p1.x, p1.y };
#pragma unroll
            for (int j = 0; j < 4; j++) {
                int o = o0 + tx * 4 + j;
                float bias = (o < 256) ? balpha[o] : 0.f;
                d_nodebuf[m * 768 + o] = vals[j] + bias;
            }
        }
    }
}

// ---------------- one channel-pass of phase C (R8-exact): accum pos/cc, emit h1 + pos ----------------
__device__ __forceinline__ void phaseC_pass(
    int c, int ph, int g, int b, const float* pe1s, float* h1s,
    const int* idxs, const float* __restrict__ bp2) {
    unsigned long long pp[8], qq[8];
#pragma unroll
    for (int jj = 0; jj < 8; jj++) { pp[jj] = 0ull; qq[jj] = 0ull; }
#pragma unroll 2
    for (int hh = 0; hh < 64; hh++) {
        float w2 = d_Wp2T[hh * 256 + c];
        float wc = d_CT[hh * 256 + c];
        unsigned long long w2p = pack2(w2, w2);
        unsigned long long wcp = pack2(wc, wc);
        const ulonglong2* pr = (const ulonglong2*)&pe1s[hh * 36 + ph * 16];
        ulonglong2 a0 = pr[0], a1 = pr[1], a2 = pr[2], a3 = pr[3];
        fma2(pp[0], w2p, a0.x); fma2(pp[1], w2p, a0.y);
        fma2(pp[2], w2p, a1.x); fma2(pp[3], w2p, a1.y);
        fma2(pp[4], w2p, a2.x); fma2(pp[5], w2p, a2.y);
        fma2(pp[6], w2p, a3.x); fma2(pp[7], w2p, a3.y);
        fma2(qq[0], wcp, a0.x); fma2(qq[1], wcp, a0.y);
        fma2(qq[2], wcp, a1.x); fma2(qq[3], wcp, a1.y);
        fma2(qq[4], wcp, a2.x); fma2(qq[5], wcp, a2.y);
        fma2(qq[6], wcp, a3.x); fma2(qq[7], wcp, a3.y);
    }
    float qg = d_nodebuf[g * 768 + 256 + c];
    float bh = d_biash[c];
    float bp = bp2[c];
    float pos[16], cc[16];
#pragma unroll
    for (int jj = 0; jj < 8; jj++) {
        float2 p = unpack2(pp[jj]); pos[2 * jj] = p.x + bp; pos[2 * jj + 1] = p.y + bp;
        float2 q = unpack2(qq[jj]); cc[2 * jj] = q.x;       cc[2 * jj + 1] = q.y;
    }
#pragma unroll
    for (int j = 0; j < 16; j++) {
        int gm = (b << 12) + idxs[ph * 16 + j];
        float kg = d_nodebuf[gm * 768 + 512 + c];
        h1s[c * 36 + ph * 16 + j] = fmaxf(cc[j] + qg - kg + bh, 0.f);
        d_pos[(g * 16 + j) * 256 + c] = pos[j];
    }
}

// ---------------- main fused attention: phase D on tensor cores (wmma tf32) ----------------
__global__ void __launch_bounds__(256, 3) pt_main_kernel(
    const float* __restrict__ xyz,
    const float* __restrict__ Wp1, const float* __restrict__ bp1,
    const float* __restrict__ bp2, const float* __restrict__ bg2,
    float* __restrict__ out) {
    __shared__ __align__(16) float pe1s[64 * 36];   // [h][jp], jp = p*16+j
    __shared__ __align__(16) float h1s[256 * 36];   // [i][jp]; reused as attn_s[32][256] in epilogue
    __shared__ float nx[32], ny[32], nz[32];
    __shared__ int idxs[32];
    __shared__ float q3[2][3];

    int g0 = blockIdx.x * 2;
    int b = g0 >> 12;
    int tid = threadIdx.x;
    int d2 = tid & 127, ph = tid >> 7;
    int c0 = d2, c1 = d2 + 128;
    int g = g0 + ph;

    if (tid < 32) idxs[tid] = d_knn[g0 * 16 + tid];
    if (tid < 6)  q3[tid / 3][tid % 3] = xyz[(g0 + tid / 3) * 3 + (tid % 3)];
    __syncthreads();
    if (tid < 96) {
        int jp = tid / 3, c = tid % 3;
        float v = xyz[((b << 12) + idxs[jp]) * 3 + c];
        if (c == 0) nx[jp] = v; else if (c == 1) ny[jp] = v; else nz[jp] = v;
    }
    __syncthreads();

    // phase B: pe1[jp][h] = relu(W_p1 rel + b_p1)
#pragma unroll
    for (int r = 0; r < 8; r++) {
        int idx = r * 256 + tid;
        int jp = idx & 31, hh = idx >> 5;
        int p = jp >> 4;
        float rx = q3[p][0] - nx[jp], ry = q3[p][1] - ny[jp], rz = q3[p][2] - nz[jp];
        float v = bp1[hh] + Wp1[hh * 3 + 0] * rx + Wp1[hh * 3 + 1] * ry + Wp1[hh * 3 + 2] * rz;
        pe1s[hh * 36 + jp] = fmaxf(v, 0.f);
    }
    __syncthreads();

    // phase C: two channel passes (register-lean); pos spilled to d_pos
    phaseC_pass(c0, ph, g, b, pe1s, h1s, idxs, bp2);
    phaseC_pass(c1, ph, g, b, pe1s, h1s, idxs, bp2);
    __syncthreads();

    // phase D (tensor cores): attn[jp][d] = sum_i h1[i][jp] * Wg2T[i][d]
    // A = h1 (col_major view: A[m=jp][k=i] at h1s[jp + i*36]), B = Wg2T row_major (k=i, n=d).
    {
        using namespace nvcuda;
        int w = tid >> 5;            // warp 0..7
        int n0 = w * 32;             // d-tile base for this warp
        wmma::fragment<wmma::accumulator, 16, 16, 8, float> acc[2][2];
#pragma unroll
        for (int mi = 0; mi < 2; mi++)
#pragma unroll
            for (int ni = 0; ni < 2; ni++) wmma::fill_fragment(acc[mi][ni], 0.f);

        for (int k0 = 0; k0 < 256; k0 += 8) {
            wmma::fragment<wmma::matrix_a, 16, 16, 8, wmma::precision::tf32, wmma::col_major> af[2];
            wmma::fragment<wmma::matrix_b, 16, 16, 8, wmma::precision::tf32, wmma::row_major> bf[2];
#pragma unroll
            for (int mi = 0; mi < 2; mi++) {
                wmma::load_matrix_sync(af[mi], h1s + k0 * 36 + mi * 16, 36);
#pragma unroll
                for (int e = 0; e < af[mi].num_elements; e++)
                    af[mi].x[e] = wmma::__float_to_tf32(af[mi].x[e]);
            }
#pragma unroll
            for (int ni = 0; ni < 2; ni++) {
                wmma::load_matrix_sync(bf[ni], d_Wg2T + k0 * 256 + n0 + ni * 16, 256);
#pragma unroll
                for (int e = 0; e < bf[ni].num_elements; e++)
                    bf[ni].x[e] = wmma::__float_to_tf32(bf[ni].x[e]);
            }
#pragma unroll
            for (int mi = 0; mi < 2; mi++)
#pragma unroll
                for (int ni = 0; ni < 2; ni++)
                    wmma::mma_sync(acc[mi][ni], af[mi], bf[ni], acc[mi][ni]);
        }
        __syncthreads();   // all warps done reading h1s
        float* attn_s = h1s;   // overlay: [32 jp][256 d] = 8192 floats <= 9216
#pragma unroll
        for (int mi = 0; mi < 2; mi++)
#pragma unroll
            for (int ni = 0; ni < 2; ni++)
                wmma::store_matrix_sync(attn_s + (mi * 16) * 256 + n0 + ni * 16,
                                        acc[mi][ni], 256, wmma::mem_row_major);
        __syncthreads();
    }

    // epilogue: read attn from attn_s, then softmax + outputs (structure unchanged)
    const float* attn_s = h1s;
    float bgA = bg2[c0], bgB = bg2[c1];
    float attnA[16], attnB[16];
#pragma unroll
    for (int j = 0; j < 16; j++) {
        attnA[j] = attn_s[(ph * 16 + j) * 256 + c0];
        attnB[j] = attn_s[(ph * 16 + j) * 256 + c1];
    }
    float mxA = -3.4e38f, mxB = -3.4e38f;
#pragma unroll
    for (int j = 0; j < 16; j++) {
        attnA[j] = (attnA[j] + bgA) * 0.0625f; mxA = fmaxf(mxA, attnA[j]);
        attnB[j] = (attnB[j] + bgB) * 0.0625f; mxB = fmaxf(mxB, attnB[j]);
    }
    float sumA = 0.f, sumB = 0.f;
#pragma unroll
    for (int j = 0; j < 16; j++) {
        attnA[j] = expf(attnA[j] - mxA); sumA += attnA[j];
        attnB[j] = expf(attnB[j] - mxB); sumB += attnB[j];
    }
    float invA = 1.f / sumA, invB = 1.f / sumB;
    float accA = 0.f, accB = 0.f;
#pragma unroll
    for (int j = 0; j < 16; j++) {
        float wA = attnA[j] * invA, wB = attnB[j] * invB;
        int gm = (b << 12) + idxs[ph * 16 + j];
        float vA = d_nodebuf[gm * 768 + c0];
        float vB = d_nodebuf[gm * 768 + c1];
        float pA = d_pos[(g * 16 + j) * 256 + c0];
        float pB = d_pos[(g * 16 + j) * 256 + c1];
        accA += wA * (vA + pA);
        accB += wB * (vB + pB);
        out[OUT_ATTN_OFF + (g * 16 + j) * 256 + c0] = wA;
        out[OUT_ATTN_OFF + (g * 16 + j) * 256 + c1] = wB;
    }
    out[g * 256 + c0] = accA;
    out[g * 256 + c1] = accB;
}

// ---------------- launch ----------------
extern "C" void kernel_launch(void* const* d_in, const int* in_sizes, int n_in,
                              void* d_out, int out_size) {
    const float* feat   = (const float*)d_in[0];
    const float* xyz    = (const float*)d_in[1];
    const float* Wphi   = (const float*)d_in[2];
    const float* bphi   = (const float*)d_in[3];
    const float* Wpsi   = (const float*)d_in[4];
    const float* bpsi   = (const float*)d_in[5];
    const float* Walpha = (const float*)d_in[6];
    const float* balpha = (const float*)d_in[7];
    const float* Wg1    = (const float*)d_in[8];
    const float* bg1    = (const float*)d_in[9];
    const float* Wg2    = (const float*)d_in[10];
    const float* bg2    = (const float*)d_in[11];
    const float* Wp1    = (const float*)d_in[12];
    const float* bp1    = (const float*)d_in[13];
    const float* Wp2    = (const float*)d_in[14];
    const float* bp2    = (const float*)d_in[15];
    float* out = (float*)d_out;

    k_fold_all<<<1376, 256>>>(Wg1, Wphi, Wpsi, Walpha, Wg2, Wp2, bg1, bphi, bpsi, bp2);
    knn_node_kernel<<<1792, 256>>>(xyz, feat, balpha);
    pt_main_kernel<<<4096, 256>>>(xyz, Wp1, bp1, bp2, bg2, out);
}